// round 16
// baseline (speedup 1.0000x reference)
#include <cuda_runtime.h>
#include <math.h>

#define NLOC 1940
#define NPRI 8732
#define BATCH 16
#define TOPK 10
#define NOBJ (BATCH*TOPK)
#define DS 64
#define IMG 300
#define ZWHAT 64
#define CPAD 4
#define TILE 16
#define NTX ((IMG + TILE - 1) / TILE)   // 19

typedef unsigned long long ull;

// ---------------- device scratch (no allocation allowed) -------------------
__device__ __align__(16) float g_decoded[NOBJ * CPAD * DS * DS];   // 10.5 MB
__device__ int   g_order[BATCH * TOPK];

// ---------------- f32x2 helpers --------------------------------------------
__device__ __forceinline__ ull pack2(float lo, float hi) {
    ull r; asm("mov.b64 %0, {%1, %2};" : "=l"(r) : "f"(lo), "f"(hi)); return r;
}
__device__ __forceinline__ void unpack2(ull v, float& a, float& b) {
    asm("mov.b64 {%0, %1}, %2;" : "=f"(a), "=f"(b) : "l"(v));
}
__device__ __forceinline__ ull ffma2(ull a, ull b, ull c) {
    ull d; asm("fma.rn.f32x2 %0, %1, %2, %3;" : "=l"(d) : "l"(a), "l"(b), "l"(c));
    return d;
}
__device__ __forceinline__ ull relu2(ull v) {
    float a, b; unpack2(v, a, b);
    return pack2(fmaxf(a, 0.f), fmaxf(b, 0.f));
}

// ---------------- index maps ------------------------------------------------
__device__ __forceinline__ int prior_to_loc(int i) {
    if (i < 5776) return i >> 2;
    if (i < 7942) return 1444 + (i - 5776) / 6;
    if (i < 8542) return 1805 + (i - 7942) / 6;
    if (i < 8692) return 1905 + (i - 8542) / 6;
    if (i < 8728) return 1930 + ((i - 8692) >> 2);
    return 1939;
}
__device__ __forceinline__ void loc_to_priors(int l, int& start, int& bpl) {
    if (l < 1444)      { start = 4 * l;                 bpl = 4; }
    else if (l < 1805) { start = 5776 + 6 * (l - 1444); bpl = 6; }
    else if (l < 1905) { start = 7942 + 6 * (l - 1805); bpl = 6; }
    else if (l < 1930) { start = 8542 + 6 * (l - 1905); bpl = 6; }
    else               { start = 8692 + 4 * (l - 1930); bpl = 4; }
}
__device__ __forceinline__ bool better(float a, int ia, float b, int ib) {
    return a > b || (a == b && ia < ib);
}
__device__ __forceinline__ void insert3(float v, int i,
                                        float& v0, int& i0, float& v1, int& i1,
                                        float& v2, int& i2) {
    if (better(v, i, v0, i0)) { v2 = v1; i2 = i1; v1 = v0; i1 = i0; v0 = v; i0 = i; }
    else if (better(v, i, v1, i1)) { v2 = v1; i2 = i1; v1 = v; i1 = i; }
    else if (better(v, i, v2, i2)) { v2 = v; i2 = i; }
}

// block-redundant top-3 locations of batch b -> prior index of rank j.
// 1024-thread version; scratch needs 1024*6 floats.
__device__ __forceinline__ int block_topk1024(const float* __restrict__ z_depth,
                                              int b, int j, float* scratch) {
    const int tid = threadIdx.x;
    float (*sv)[3] = (float(*)[3])scratch;
    int   (*si)[3] = (int(*)[3])(scratch + 1024 * 3);

    float v0 = -INFINITY, v1 = -INFINITY, v2 = -INFINITY;
    int   i0 = 0x7fffffff, i1 = 0x7fffffff, i2 = 0x7fffffff;
    const float4* __restrict__ zd4 =
        reinterpret_cast<const float4*>(z_depth + b * NLOC);
    for (int i = tid; i < NLOC / 4; i += 1024) {
        const float4 v = __ldg(zd4 + i);
        insert3(v.x, 4 * i + 0, v0, i0, v1, i1, v2, i2);
        insert3(v.y, 4 * i + 1, v0, i0, v1, i1, v2, i2);
        insert3(v.z, 4 * i + 2, v0, i0, v1, i1, v2, i2);
        insert3(v.w, 4 * i + 3, v0, i0, v1, i1, v2, i2);
    }
    sv[tid][0] = v0; sv[tid][1] = v1; sv[tid][2] = v2;
    si[tid][0] = i0; si[tid][1] = i1; si[tid][2] = i2;
    __syncthreads();
    for (int s = 512; s > 0; s >>= 1) {
        if (tid < s) {
            #pragma unroll
            for (int q = 0; q < 3; q++)
                insert3(sv[tid + s][q], si[tid + s][q], v0, i0, v1, i1, v2, i2);
            sv[tid][0] = v0; sv[tid][1] = v1; sv[tid][2] = v2;
            si[tid][0] = i0; si[tid][1] = i1; si[tid][2] = i2;
        }
        __syncthreads();
    }
    __shared__ int s_ord;
    if (tid == 0) {
        int ranks[3] = { i0, i1, i2 };
        int ord = -1, cnt = 0;
        #pragma unroll
        for (int r = 0; r < 3; r++) {
            int start, bpl;
            loc_to_priors(ranks[r], start, bpl);
            if (ord < 0 && j < cnt + bpl) ord = start + (j - cnt);
            cnt += bpl;
        }
        s_ord = ord;
    }
    __syncthreads();
    return s_ord;
}

// ---------------------------------------------------------------------------
// Decode kernel: topk + present-skip + L0..L5, one block per object, 1024 thr.
// L2..L4 use XS=4 spatial split; L0/L1 use split-K x2 (group 1 parks packed
// partials in smem P; group 0 adds via ffma2 with (1,1)).
// smem: bufA 8192 fl (32KB) | bufB 16384 fl (64KB) | P 2048 fl (8KB)
// ---------------------------------------------------------------------------
__global__ void __launch_bounds__(1024, 1) decode_kernel(
    const float* __restrict__ z_depth,
    const float* __restrict__ z_what,
    const int*   __restrict__ z_present,
    const float* __restrict__ W0, const float* __restrict__ b0,
    const float* __restrict__ W1, const float* __restrict__ b1,
    const float* __restrict__ W2, const float* __restrict__ b2,
    const float* __restrict__ W3, const float* __restrict__ b3,
    const float* __restrict__ W4, const float* __restrict__ b4,
    const float* __restrict__ W5, const float* __restrict__ b5)
{
    extern __shared__ __align__(16) float sm[];
    float* bufA = sm;              // 8192 floats
    float* bufB = sm + 8192;       // 16384 floats
    ull*   P    = reinterpret_cast<ull*>(sm + 8192 + 16384);  // 1024 ull

    const int m = blockIdx.x;
    const int b = m / TOPK;
    const int j = m % TOPK;
    const int tid = threadIdx.x;

    const int ord = block_topk1024(z_depth, b, j, bufB);
    if (tid == 0) g_order[m] = ord;

    // present-skip: composite never reads texels of non-present objects
    if (__ldg(z_present + b * NPRI + ord) != 1) return;

    const int loc = prior_to_loc(ord);
    const float* src = z_what + (size_t)(b * NLOC + loc) * ZWHAT;
    if (tid < ZWHAT) bufA[tid] = src[tid];
    __syncthreads();

    const ull ONE2 = pack2(1.0f, 1.0f);

    // ---- L0: 64 -> 256 ch, 1x1 -> 2x2. split-K x2 over threads 0..511 ----
    {
        ull acc01 = 0ULL, acc23 = 0ULL;
        const int o = tid & 255;
        const int cg = tid >> 8;       // 0 or 1 (tid < 512)
        if (tid < 512) {
            const ulonglong2* __restrict__ W0q =
                reinterpret_cast<const ulonglong2*>(W0);
            if (cg == 0) {
                const float bo = __ldg(b0 + o);
                acc01 = pack2(bo, bo); acc23 = acc01;
            }
            const int c0 = cg * 32;
            #pragma unroll 8
            for (int c = c0; c < c0 + 32; c++) {
                const ulonglong2 wq = __ldg(W0q + c * 256 + o);
                const float iv = bufA[c];
                const ull d = pack2(iv, iv);
                acc01 = ffma2(d, wq.x, acc01);
                acc23 = ffma2(d, wq.y, acc23);
            }
            if (cg == 1) { P[o * 2] = acc01; P[o * 2 + 1] = acc23; }
        }
        __syncthreads();
        if (tid < 256) {   // cg == 0 holders
            acc01 = ffma2(P[o * 2],     ONE2, acc01);
            acc23 = ffma2(P[o * 2 + 1], ONE2, acc23);
            ull* ob = reinterpret_cast<ull*>(bufB) + o * 2;
            ob[0] = relu2(acc01);   // [o][0][0..1]
            ob[1] = relu2(acc23);   // [o][1][0..1]
        }
    }
    __syncthreads();

    // ---- L1: 256 -> 128 ch, 2x2 -> 4x4. split-K x2 (512 spatial slots) ----
    {
        const int o = tid & 127;
        const int rem = (tid >> 7) & 3;   // 0..3
        const int y = rem & 1, x = rem >> 1;
        const int cg = tid >> 9;          // 0 or 1
        const ulonglong2* __restrict__ W1q =
            reinterpret_cast<const ulonglong2*>(W1);
        ull acc01 = 0ULL, acc23 = 0ULL;
        if (cg == 0) {
            const float bo = __ldg(b1 + o);
            acc01 = pack2(bo, bo); acc23 = acc01;
        }
        const int c0 = cg * 128;
        #pragma unroll 4
        for (int c = c0; c < c0 + 128; c++) {
            const ulonglong2 wq = __ldg(W1q + c * 128 + o);
            const float iv = bufB[c * 4 + y * 2 + x];
            const ull d = pack2(iv, iv);
            acc01 = ffma2(d, wq.x, acc01);
            acc23 = ffma2(d, wq.y, acc23);
        }
        if (cg == 1) { P[(tid - 512) * 2] = acc01; P[(tid - 512) * 2 + 1] = acc23; }
        __syncthreads();
        if (tid < 512) {
            acc01 = ffma2(P[tid * 2],     ONE2, acc01);
            acc23 = ffma2(P[tid * 2 + 1], ONE2, acc23);
            ull* oa = reinterpret_cast<ull*>(bufA);
            oa[(o * 4 + 2 * y) * 2 + x]     = relu2(acc01);   // row 2y
            oa[(o * 4 + 2 * y + 1) * 2 + x] = relu2(acc23);   // row 2y+1
        }
    }
    __syncthreads();

    // ---- L2: 128 -> 64 ch, 4x4 -> 8x8. XS=4, PX=1, all 1024 threads ----
    {
        const int o = tid & 63;
        const int rem = tid >> 6;         // 0..15
        const int y = rem & 3, x = rem >> 2;   // x 0..3
        const ulonglong2* __restrict__ W2q =
            reinterpret_cast<const ulonglong2*>(W2);
        const float bo = __ldg(b2 + o);
        ull acc01 = pack2(bo, bo), acc23 = acc01;
        #pragma unroll 4
        for (int c = 0; c < 128; c++) {
            const ulonglong2 wq = __ldg(W2q + c * 64 + o);
            const float iv = bufA[c * 16 + y * 4 + x];
            const ull d = pack2(iv, iv);
            acc01 = ffma2(d, wq.x, acc01);
            acc23 = ffma2(d, wq.y, acc23);
        }
        ull* ob = reinterpret_cast<ull*>(bufB);
        ob[(o * 8 + 2 * y) * 4 + x]     = relu2(acc01);
        ob[(o * 8 + 2 * y + 1) * 4 + x] = relu2(acc23);
    }
    __syncthreads();

    // ---- L3: 64 -> 32 ch, 8x8 -> 16x16. XS=4, PX=2 ----
    {
        const int o = tid & 31;
        const int rem = tid >> 5;         // 0..31
        const int y = rem & 7, xh = rem >> 3;  // xh 0..3, pixels 2xh, 2xh+1
        const int x0 = 2 * xh;
        const ulonglong2* __restrict__ W3q =
            reinterpret_cast<const ulonglong2*>(W3);
        const float bo = __ldg(b3 + o);
        const ull bb = pack2(bo, bo);
        ull a01[2] = { bb, bb }, a23[2] = { bb, bb };
        const ull* __restrict__ ibd = reinterpret_cast<const ull*>(bufB);
        #pragma unroll 4
        for (int c = 0; c < 64; c++) {
            const ulonglong2 wq = __ldg(W3q + c * 32 + o);
            const ull iv2 = ibd[c * 32 + y * 4 + xh];
            float i0, i1; unpack2(iv2, i0, i1);
            const ull d0 = pack2(i0, i0);
            const ull d1 = pack2(i1, i1);
            a01[0] = ffma2(d0, wq.x, a01[0]);
            a23[0] = ffma2(d0, wq.y, a23[0]);
            a01[1] = ffma2(d1, wq.x, a01[1]);
            a23[1] = ffma2(d1, wq.y, a23[1]);
        }
        ull* oa = reinterpret_cast<ull*>(bufA);
        ull* r0 = oa + (o * 16 + 2 * y) * 8;
        ull* r1 = oa + (o * 16 + 2 * y + 1) * 8;
        r0[x0] = relu2(a01[0]); r0[x0 + 1] = relu2(a01[1]);
        r1[x0] = relu2(a23[0]); r1[x0 + 1] = relu2(a23[1]);
    }
    __syncthreads();

    // ---- L4: 32 -> 16 ch, 16x16 -> 32x32. XS=4, PX=4 ----
    {
        const int o = tid & 15;
        const int rem = tid >> 4;         // 0..63
        const int y = rem & 15, xq = rem >> 4;  // xq 0..3, pixels 4xq..4xq+3
        const int x0 = 4 * xq;
        const ulonglong2* __restrict__ W4q =
            reinterpret_cast<const ulonglong2*>(W4);
        const float bo = __ldg(b4 + o);
        const ull bb = pack2(bo, bo);
        ull a01[4], a23[4];
        #pragma unroll
        for (int p = 0; p < 4; p++) { a01[p] = bb; a23[p] = bb; }
        const ull* __restrict__ iad = reinterpret_cast<const ull*>(bufA);
        #pragma unroll 4
        for (int c = 0; c < 32; c++) {
            const ulonglong2 wq = __ldg(W4q + c * 16 + o);
            const int ib = c * 128 + y * 8 + 2 * xq;
            #pragma unroll
            for (int pp = 0; pp < 2; pp++) {
                const ull iv2 = iad[ib + pp];
                float i0, i1; unpack2(iv2, i0, i1);
                const ull d0 = pack2(i0, i0);
                const ull d1 = pack2(i1, i1);
                a01[2 * pp]     = ffma2(d0, wq.x, a01[2 * pp]);
                a23[2 * pp]     = ffma2(d0, wq.y, a23[2 * pp]);
                a01[2 * pp + 1] = ffma2(d1, wq.x, a01[2 * pp + 1]);
                a23[2 * pp + 1] = ffma2(d1, wq.y, a23[2 * pp + 1]);
            }
        }
        ull* ob = reinterpret_cast<ull*>(bufB);
        ull* r0 = ob + (o * 32 + 2 * y) * 16;
        ull* r1 = ob + (o * 32 + 2 * y + 1) * 16;
        #pragma unroll
        for (int p = 0; p < 4; p++) {
            r0[x0 + p] = relu2(a01[p]);
            r1[x0 + p] = relu2(a23[p]);
        }
    }
    __syncthreads();

    // stage W5+b5 into bufA (free after L4 consumed it)
    if (tid < 192) bufA[tid] = __ldg(W5 + tid);
    if (tid < 3)   bufA[192 + tid] = __ldg(b5 + tid);
    __syncthreads();

    // ---- L5: 16 -> 3 ch, sigmoid, CPAD texels; 1 src px per thread ----
    {
        const int sy = tid >> 5;         // 0..31
        const int sx = tid & 31;         // 0..31
        const ulonglong2* __restrict__ w5u =
            reinterpret_cast<const ulonglong2*>(bufA);
        ull a01[3], a23[3];
        #pragma unroll
        for (int o = 0; o < 3; o++) {
            a01[o] = pack2(bufA[192 + o], bufA[192 + o]);
            a23[o] = a01[o];
        }
        #pragma unroll 4
        for (int c = 0; c < 16; c++) {
            const float iv = bufB[c * 1024 + tid];
            const ull d = pack2(iv, iv);
            #pragma unroll
            for (int o = 0; o < 3; o++) {
                const ulonglong2 wq = w5u[c * 3 + o];
                a01[o] = ffma2(d, wq.x, a01[o]);
                a23[o] = ffma2(d, wq.y, a23[o]);
            }
        }
        float r00[3], r01[3], r10[3], r11[3];
        #pragma unroll
        for (int o = 0; o < 3; o++) {
            float v00, v01, v10, v11;
            unpack2(a01[o], v00, v01);
            unpack2(a23[o], v10, v11);
            r00[o] = 1.0f / (1.0f + __expf(-v00));
            r01[o] = 1.0f / (1.0f + __expf(-v01));
            r10[o] = 1.0f / (1.0f + __expf(-v10));
            r11[o] = 1.0f / (1.0f + __expf(-v11));
        }
        float4* g4 = reinterpret_cast<float4*>(g_decoded) + (size_t)m * DS * DS;
        const int row0 = 2 * sy, col0 = 2 * sx;
        g4[row0 * DS + col0]           = make_float4(r00[0], r00[1], r00[2], 0.f);
        g4[row0 * DS + col0 + 1]       = make_float4(r01[0], r01[1], r01[2], 0.f);
        g4[(row0 + 1) * DS + col0]     = make_float4(r10[0], r10[1], r10[2], 0.f);
        g4[(row0 + 1) * DS + col0 + 1] = make_float4(r11[0], r11[1], r11[2], 0.f);
    }
}

// ---------------------------------------------------------------------------
// Composite: fused STN + depth-ordered first-nonzero (unchanged, stable).
// ---------------------------------------------------------------------------
__global__ void __launch_bounds__(256) composite_kernel(
    const float* __restrict__ z_where,
    const int*   __restrict__ z_present,
    float* __restrict__ out)
{
    const int b = blockIdx.y;
    const int tx0 = (blockIdx.x % NTX) * TILE;
    const int ty0 = (blockIdx.x / NTX) * TILE;

    __shared__ float s_sx[TOPK], s_ox[TOPK], s_sy[TOPK], s_oy[TOPK];
    __shared__ int   s_flag[TOPK];
    __shared__ int   s_list[TOPK];
    __shared__ int   s_nc;

    const int tid = threadIdx.x;
    if (tid < TOPK) {
        const int ord = g_order[b * TOPK + tid];
        const float* zw = z_where + (size_t)(b * NPRI + ord) * 4;
        const float cx = zw[0], cy = zw[1];
        const float w = zw[2] + 1e-6f, h = zw[3] + 1e-6f;
        const float half = (float)DS * 0.5f;
        const float xsn = half / w;
        const float ysn = half / h;
        const float sx = xsn * (2.0f / (float)IMG);
        const float ox = half - 0.5f
                         + xsn * ((1.0f / (float)IMG - 1.0f) - (2.0f * cx - 1.0f));
        const float sy = ysn * (2.0f / (float)IMG);
        const float oy = half - 0.5f
                         + ysn * ((1.0f / (float)IMG - 1.0f) - (2.0f * cy - 1.0f));
        s_sx[tid] = sx; s_ox[tid] = ox; s_sy[tid] = sy; s_oy[tid] = oy;
        const float ix_lo = fmaf((float)tx0, sx, ox);
        const float ix_hi = fmaf((float)(tx0 + TILE - 1), sx, ox);
        const float iy_lo = fmaf((float)ty0, sy, oy);
        const float iy_hi = fmaf((float)(ty0 + TILE - 1), sy, oy);
        const bool pres = (z_present[b * NPRI + ord] == 1);
        s_flag[tid] = (pres &&
                       ix_hi >= -1.01f && ix_lo < 64.01f &&
                       iy_hi >= -1.01f && iy_lo < 64.01f) ? 1 : 0;
    }
    __syncthreads();
    if (tid == 0) {
        int nc = 0;
        #pragma unroll
        for (int k = 0; k < TOPK; k++)
            if (s_flag[k]) s_list[nc++] = k;
        s_nc = nc;
    }
    __syncthreads();

    const int x = tx0 + (tid % TILE);
    const int y = ty0 + (tid / TILE);
    if (x >= IMG || y >= IMG) return;
    const float fx = (float)x, fy = (float)y;

    float r0 = 0.0f, r1 = 0.0f, r2 = 0.0f;
    int done = 0;
    const int nc = s_nc;

    for (int kk = 0; kk < nc; kk++) {
        const int k = s_list[kk];
        const float ix = fmaf(fx, s_sx[k], s_ox[k]);
        const float iy = fmaf(fy, s_sy[k], s_oy[k]);
        const float ix0f = floorf(ix), iy0f = floorf(iy);
        if (!(ix0f >= -1.0f && ix0f <= 63.0f && iy0f >= -1.0f && iy0f <= 63.0f))
            continue;
        const float wx1 = ix - ix0f, wy1 = iy - iy0f;
        const float wx0 = 1.0f - wx1, wy0 = 1.0f - wy1;
        const int ix0 = (int)ix0f, iy0 = (int)iy0f;
        const bool vx0 = (ix0 >= 0), vx1 = (ix0 <= 62);
        const bool vy0 = (iy0 >= 0), vy1 = (iy0 <= 62);
        const float w00 = (vy0 && vx0) ? wy0 * wx0 : 0.0f;
        const float w01 = (vy0 && vx1) ? wy0 * wx1 : 0.0f;
        const float w10 = (vy1 && vx0) ? wy1 * wx0 : 0.0f;
        const float w11 = (vy1 && vx1) ? wy1 * wx1 : 0.0f;
        const int x0c = max(ix0, 0),     x1c = min(ix0 + 1, DS - 1);
        const int y0c = max(iy0, 0),     y1c = min(iy0 + 1, DS - 1);
        const int i00 = y0c * DS + x0c, i01 = y0c * DS + x1c;
        const int i10 = y1c * DS + x0c, i11 = y1c * DS + x1c;
        const float4* __restrict__ base = reinterpret_cast<const float4*>(g_decoded)
                                          + (size_t)(b * TOPK + k) * DS * DS;
        const float4 t00 = __ldg(base + i00);
        const float4 t01 = __ldg(base + i01);
        const float4 t10 = __ldg(base + i10);
        const float4 t11 = __ldg(base + i11);

        const float s0 = t00.x * w00 + t01.x * w01 + t10.x * w10 + t11.x * w11;
        const float s1 = t00.y * w00 + t01.y * w01 + t10.y * w10 + t11.y * w11;
        const float s2 = t00.z * w00 + t01.z * w01 + t10.z * w10 + t11.z * w11;

        if (!(done & 1) && s0 != 0.0f) { r0 = s0; done |= 1; }
        if (!(done & 2) && s1 != 0.0f) { r1 = s1; done |= 2; }
        if (!(done & 4) && s2 != 0.0f) { r2 = s2; done |= 4; }
        if (done == 7) break;
    }

    const size_t pix = (size_t)y * IMG + x;
    out[((size_t)(b * 3 + 0) * IMG * IMG) + pix] = r0;
    out[((size_t)(b * 3 + 1) * IMG * IMG) + pix] = r1;
    out[((size_t)(b * 3 + 2) * IMG * IMG) + pix] = r2;
}

// ---------------------------------------------------------------------------
extern "C" void kernel_launch(void* const* d_in, const int* in_sizes, int n_in,
                              void* d_out, int out_size)
{
    const float* z_what    = (const float*)d_in[0];
    const float* z_where   = (const float*)d_in[1];
    const int*   z_present = (const int*)  d_in[2];
    const float* z_depth   = (const float*)d_in[3];
    const float* W0 = (const float*)d_in[4];  const float* b0 = (const float*)d_in[5];
    const float* W1 = (const float*)d_in[6];  const float* b1 = (const float*)d_in[7];
    const float* W2 = (const float*)d_in[8];  const float* b2 = (const float*)d_in[9];
    const float* W3 = (const float*)d_in[10]; const float* b3 = (const float*)d_in[11];
    const float* W4 = (const float*)d_in[12]; const float* b4 = (const float*)d_in[13];
    const float* W5 = (const float*)d_in[14]; const float* b5 = (const float*)d_in[15];
    float* out = (float*)d_out;

    const int smem_bytes = (8192 + 16384 + 2048) * sizeof(float);   // 104 KB
    static bool attr_set = false;
    if (!attr_set) {
        cudaFuncSetAttribute(decode_kernel,
                             cudaFuncAttributeMaxDynamicSharedMemorySize,
                             smem_bytes);
        attr_set = true;
    }

    decode_kernel<<<NOBJ, 1024, smem_bytes>>>(
        z_depth, z_what, z_present,
        W0, b0, W1, b1, W2, b2, W3, b3, W4, b4, W5, b5);

    dim3 cgrid(NTX * NTX, BATCH);
    composite_kernel<<<cgrid, 256>>>(z_where, z_present, out);
}